// round 5
// baseline (speedup 1.0000x reference)
#include <cuda_runtime.h>
#include <cuda_bf16.h>
#include <cstdint>
#include <cstddef>

// smem regions (bytes, base-relative)
#define R0 0u          // x tile [128][168] hi|lo (86016) / e tile [128][136] hi|lo (69632)
#define R1 86016u      // weight tile: wg 86016, others 69632 ; f2 buf
#define R2 155648u     // xi tile [128][136] hi|lo (69632)  (pass2 only)
#define SMEM_TOTAL 225280
#define ST_X 336       // x row stride bytes (168 bf16)
#define ST_E 272       // e/xi/weight row stride bytes (136 bf16)

// ---------------------------------------------------------------- helpers
__device__ __forceinline__ uint32_t smem_to_u32(const void* p) {
    uint32_t a;
    asm("{ .reg .u64 t; cvta.to.shared.u64 t, %1; cvt.u32.u64 %0, t; }"
        : "=r"(a) : "l"(p));
    return a;
}
__device__ __forceinline__ float lrelu(float x) { return x > 0.f ? x : 0.01f * x; }
__device__ __forceinline__ uint32_t pk(__nv_bfloat16 a, __nv_bfloat16 b) {
    __nv_bfloat162 t; t.x = a; t.y = b;
    return *reinterpret_cast<uint32_t*>(&t);
}
// split two floats into bf16 hi-pair and lo-pair
__device__ __forceinline__ void sp2(float a, float b, uint32_t& h, uint32_t& l) {
    __nv_bfloat16 h0 = __float2bfloat16(a), h1 = __float2bfloat16(b);
    __nv_bfloat16 l0 = __float2bfloat16(a - __bfloat162float(h0));
    __nv_bfloat16 l1 = __float2bfloat16(b - __bfloat162float(h1));
    h = pk(h0, h1); l = pk(l0, l1);
}
__device__ __forceinline__ void cpy(void* dst, const void* src, int nbytes, int tid) {
    uint4* d4 = (uint4*)dst;
    const uint4* s4 = (const uint4*)src;
    int n = nbytes >> 4;
    for (int i = tid; i < n; i += 256) d4[i] = s4[i];
}

#define LDSM4(r, a) \
    asm volatile("ldmatrix.sync.aligned.m8n8.x4.shared.b16 {%0,%1,%2,%3}, [%4];" \
        : "=r"((r)[0]), "=r"((r)[1]), "=r"((r)[2]), "=r"((r)[3]) : "r"(a))

#define MMA(c, av, b0, b1) \
    asm volatile("mma.sync.aligned.m16n8k16.row.col.f32.bf16.bf16.f32 " \
        "{%0,%1,%2,%3},{%4,%5,%6,%7},{%8,%9},{%0,%1,%2,%3};" \
        : "+f"((c)[0]), "+f"((c)[1]), "+f"((c)[2]), "+f"((c)[3]) \
        : "r"((av)[0]), "r"((av)[1]), "r"((av)[2]), "r"((av)[3]), "r"(b0), "r"(b1))

// ------------------------------------------------------------------- scratch
__device__ __align__(16) char g_wg[8 * 86016];       // [n=128][k=168 pad] hi|lo
__device__ __align__(16) char g_wv[69632];           // [128][136] hi|lo
__device__ __align__(16) char g_wf1[8 * 139264];     // per agent: part0 hi|lo, part1 hi|lo
__device__ __align__(16) char g_escr[285212672];     // 512 tiles x 8 agents x 69632

// --------------------------------------------------------------- prep kernel
#define NWG (8 * 160 * 128)
#define NWV (128 * 128)
#define NWF (8 * 256 * 128)
#define NPREP (NWG + NWV + NWF)

__global__ void prep_kernel(const float* __restrict__ Wg,
                            const float* __restrict__ Wv,
                            const float* __restrict__ Wf1) {
    int i = blockIdx.x * blockDim.x + threadIdx.x;
    if (i >= NPREP) return;
    float v; char* base; int losz, n, k, str;
    if (i < NWG) {
        int a = i / 20480, r = i - a * 20480;
        k = r >> 7; n = r & 127;                       // k 0..159
        v = Wg[(size_t)a * 20480 + (size_t)k * 128 + n];
        base = g_wg + (size_t)a * 86016; losz = 43008; str = ST_X;
    } else if (i < NWG + NWV) {
        int t = i - NWG;
        k = t >> 7; n = t & 127;
        v = Wv[(size_t)(n >> 5) * 4096 + (size_t)k * 32 + (n & 31)];
        base = g_wv; losz = 34816; str = ST_E;
    } else {
        int t = i - NWG - NWV;
        int a = t >> 15, r = t & 32767;
        int ii = r >> 7; n = r & 127;
        int part = ii >> 7; k = ii & 127;
        v = Wf1[(size_t)a * 32768 + (size_t)ii * 128 + n];
        base = g_wf1 + (size_t)a * 139264 + (size_t)part * 69632;
        losz = 34816; str = ST_E;
    }
    __nv_bfloat16 h = __float2bfloat16(v);
    __nv_bfloat16 l = __float2bfloat16(v - __bfloat162float(h));
    *(__nv_bfloat16*)(base + (size_t)n * str + k * 2) = h;
    *(__nv_bfloat16*)(base + losz + (size_t)n * str + k * 2) = l;
}

// --------------------------------------------------------- warp-tiled GEMM
// C[128,128] (+)= A[128,K] * B[128,K]^T with 2-way bf16 split (hh+hl+lh).
// 8 warps: wm=wid&1 (64-row half), wn=wid>>1 (32-col quarter).
__device__ __forceinline__ void gemm_run(uint32_t sb,
                                         uint32_t aHi, uint32_t aLo, int aStr,
                                         uint32_t bHi, uint32_t bLo, int bStr,
                                         int nks, float (&acc)[4][4][4], bool init,
                                         int wm, int wn, int lane) {
    if (init)
#pragma unroll
        for (int im = 0; im < 4; im++)
#pragma unroll
            for (int in = 0; in < 4; in++)
#pragma unroll
                for (int e = 0; e < 4; e++) acc[im][in][e] = 0.f;
    uint32_t aRow = (uint32_t)(wm * 64 + (lane & 15));
    uint32_t bRow = (uint32_t)(wn * 32 + (lane & 15));
    uint32_t colo = (uint32_t)((lane >> 4) * 16);
    for (int ks = 0; ks < nks; ks++) {
        uint32_t co = (uint32_t)ks * 32 + colo;
        uint32_t ah[4][4], al[4][4], bh[2][4], bl[2][4];
#pragma unroll
        for (int im = 0; im < 4; im++) {
            uint32_t r = (aRow + im * 16) * (uint32_t)aStr + co;
            LDSM4(ah[im], sb + aHi + r);
            LDSM4(al[im], sb + aLo + r);
        }
#pragma unroll
        for (int ip = 0; ip < 2; ip++) {
            uint32_t r = (bRow + ip * 16) * (uint32_t)bStr + co;
            LDSM4(bh[ip], sb + bHi + r);
            LDSM4(bl[ip], sb + bLo + r);
        }
#pragma unroll
        for (int im = 0; im < 4; im++)
#pragma unroll
            for (int in = 0; in < 4; in++) {
                uint32_t b0h = bh[in >> 1][in & 1], b1h = bh[in >> 1][(in & 1) + 2];
                uint32_t b0l = bl[in >> 1][in & 1], b1l = bl[in >> 1][(in & 1) + 2];
                MMA(acc[im][in], ah[im], b0h, b1h);
                MMA(acc[im][in], ah[im], b0l, b1l);
                MMA(acc[im][in], al[im], b0h, b1h);
            }
    }
}

// ----------------------------------------------------------------- main
__global__ __launch_bounds__(256, 1)
void critic_main(const float* __restrict__ obs, const float* __restrict__ act,
                 const float* __restrict__ bg, const float* __restrict__ bvv,
                 const float* __restrict__ bf1, const float* __restrict__ wf2,
                 const float* __restrict__ bf2, float* __restrict__ out) {
    extern __shared__ __align__(16) char sm[];
    uint32_t sb = smem_to_u32(sm);
    int tid = threadIdx.x;
    int lane = tid & 31, wid = tid >> 5;
    int wm = wid & 1, wn = wid >> 1;
    int g = lane >> 2, t4 = lane & 3;
    int tile = blockIdx.x;

    float acc[4][4][4];
    float S[4][4][4];

    // ============================ PASS 1 ============================
    for (int a = 0; a < 8; a++) {
        __syncthreads();
        // load x rows -> padded hi/lo smem tile
        {
            int row = tid >> 1, half = tid & 1;
            size_t rb = (size_t)a * 65536 + (size_t)tile * 128 + row;
            const float4* op = (const float4*)(obs + rb * 128) + half * 16;
            const float4* ap = (const float4*)(act + rb * 32) + half * 4;
            char* hb = sm + R0 + (size_t)row * ST_X;
            char* lb = hb + 43008;
#pragma unroll 4
            for (int i = 0; i < 16; i++) {
                float4 f = __ldg(op + i);
                int k = half * 64 + i * 4;
                uint32_t h0, l0, h1, l1;
                sp2(f.x, f.y, h0, l0); sp2(f.z, f.w, h1, l1);
                *(uint2*)(hb + k * 2) = make_uint2(h0, h1);
                *(uint2*)(lb + k * 2) = make_uint2(l0, l1);
            }
#pragma unroll
            for (int i = 0; i < 4; i++) {
                float4 f = __ldg(ap + i);
                int k = 128 + half * 16 + i * 4;
                uint32_t h0, l0, h1, l1;
                sp2(f.x, f.y, h0, l0); sp2(f.z, f.w, h1, l1);
                *(uint2*)(hb + k * 2) = make_uint2(h0, h1);
                *(uint2*)(lb + k * 2) = make_uint2(l0, l1);
            }
        }
        cpy(sm + R1, g_wg + (size_t)a * 86016, 86016, tid);
        __syncthreads();
        gemm_run(sb, R0, R0 + 43008, ST_X, R1, R1 + 43008, ST_X, 10, acc, true, wm, wn, lane);
        __syncthreads();
        // e = lrelu(acc + bg) -> hi/lo smem tile (overwrites x)
        {
            const float* bga = bg + a * 128;
#pragma unroll
            for (int im = 0; im < 4; im++)
#pragma unroll
                for (int in = 0; in < 4; in++) {
                    int c = wn * 32 + in * 8 + t4 * 2;
                    int r0 = wm * 64 + im * 16 + g;
                    float b0 = __ldg(bga + c), b1 = __ldg(bga + c + 1);
                    uint32_t h, l;
                    sp2(lrelu(acc[im][in][0] + b0), lrelu(acc[im][in][1] + b1), h, l);
                    *(uint32_t*)(sm + R0 + (size_t)r0 * ST_E + c * 2) = h;
                    *(uint32_t*)(sm + R0 + 34816 + (size_t)r0 * ST_E + c * 2) = l;
                    sp2(lrelu(acc[im][in][2] + b0), lrelu(acc[im][in][3] + b1), h, l);
                    *(uint32_t*)(sm + R0 + (size_t)(r0 + 8) * ST_E + c * 2) = h;
                    *(uint32_t*)(sm + R0 + 34816 + (size_t)(r0 + 8) * ST_E + c * 2) = l;
                }
        }
        __syncthreads();
        cpy(g_escr + ((size_t)tile * 8 + a) * 69632, sm + R0, 69632, tid);
        cpy(sm + R1, g_wv, 69632, tid);
        __syncthreads();
        gemm_run(sb, R0, R0 + 34816, ST_E, R1, R1 + 34816, ST_E, 8, acc, true, wm, wn, lane);
        // S += lrelu(v + bv)
#pragma unroll
        for (int im = 0; im < 4; im++)
#pragma unroll
            for (int in = 0; in < 4; in++) {
                int c = wn * 32 + in * 8 + t4 * 2;
                float b0 = __ldg(bvv + c), b1 = __ldg(bvv + c + 1);
                float v0 = lrelu(acc[im][in][0] + b0), v1 = lrelu(acc[im][in][1] + b1);
                float v2 = lrelu(acc[im][in][2] + b0), v3 = lrelu(acc[im][in][3] + b1);
                if (a == 0) {
                    S[im][in][0] = v0; S[im][in][1] = v1;
                    S[im][in][2] = v2; S[im][in][3] = v3;
                } else {
                    S[im][in][0] += v0; S[im][in][1] += v1;
                    S[im][in][2] += v2; S[im][in][3] += v3;
                }
            }
    }

    // ============================ PASS 2 ============================
    for (int a = 0; a < 8; a++) {
        __syncthreads();
        cpy(sm + R0, g_escr + ((size_t)tile * 8 + a) * 69632, 69632, tid);
        cpy(sm + R1, g_wv, 69632, tid);
        __syncthreads();
        gemm_run(sb, R0, R0 + 34816, ST_E, R1, R1 + 34816, ST_E, 8, acc, true, wm, wn, lane);
        // xi = S - lrelu(v+bv) -> R2 hi/lo
#pragma unroll
        for (int im = 0; im < 4; im++)
#pragma unroll
            for (int in = 0; in < 4; in++) {
                int c = wn * 32 + in * 8 + t4 * 2;
                int r0 = wm * 64 + im * 16 + g;
                float b0 = __ldg(bvv + c), b1 = __ldg(bvv + c + 1);
                float x0 = S[im][in][0] - lrelu(acc[im][in][0] + b0);
                float x1 = S[im][in][1] - lrelu(acc[im][in][1] + b1);
                float x2 = S[im][in][2] - lrelu(acc[im][in][2] + b0);
                float x3 = S[im][in][3] - lrelu(acc[im][in][3] + b1);
                uint32_t h, l;
                sp2(x0, x1, h, l);
                *(uint32_t*)(sm + R2 + (size_t)r0 * ST_E + c * 2) = h;
                *(uint32_t*)(sm + R2 + 34816 + (size_t)r0 * ST_E + c * 2) = l;
                sp2(x2, x3, h, l);
                *(uint32_t*)(sm + R2 + (size_t)(r0 + 8) * ST_E + c * 2) = h;
                *(uint32_t*)(sm + R2 + 34816 + (size_t)(r0 + 8) * ST_E + c * 2) = l;
            }
        __syncthreads();
        cpy(sm + R1, g_wf1 + (size_t)a * 139264, 69632, tid);   // Wf1 part0 (xi)
        __syncthreads();
        gemm_run(sb, R2, R2 + 34816, ST_E, R1, R1 + 34816, ST_E, 8, acc, true, wm, wn, lane);
        __syncthreads();
        cpy(sm + R1, g_wf1 + (size_t)a * 139264 + 69632, 69632, tid);  // part1 (e)
        __syncthreads();
        gemm_run(sb, R0, R0 + 34816, ST_E, R1, R1 + 34816, ST_E, 8, acc, false, wm, wn, lane);
        __syncthreads();
        // f2: per-row dot( lrelu(h1+bf1), wf2 )
        {
            float part[8];
#pragma unroll
            for (int i = 0; i < 8; i++) part[i] = 0.f;
            const float* b1a = bf1 + a * 128;
            const float* w2a = wf2 + a * 128;
#pragma unroll
            for (int im = 0; im < 4; im++)
#pragma unroll
                for (int in = 0; in < 4; in++) {
                    int c = wn * 32 + in * 8 + t4 * 2;
                    float b0 = __ldg(b1a + c), b1 = __ldg(b1a + c + 1);
                    float w0 = __ldg(w2a + c), w1 = __ldg(w2a + c + 1);
                    part[im * 2 + 0] += lrelu(acc[im][in][0] + b0) * w0
                                      + lrelu(acc[im][in][1] + b1) * w1;
                    part[im * 2 + 1] += lrelu(acc[im][in][2] + b0) * w0
                                      + lrelu(acc[im][in][3] + b1) * w1;
                }
#pragma unroll
            for (int i = 0; i < 8; i++) {
                part[i] += __shfl_xor_sync(0xffffffffu, part[i], 1);
                part[i] += __shfl_xor_sync(0xffffffffu, part[i], 2);
            }
            if (t4 == 0) {
#pragma unroll
                for (int i = 0; i < 8; i++) {
                    int row = wm * 64 + (i >> 1) * 16 + g + (i & 1) * 8;
                    ((float*)(sm + R1))[row * 4 + wn] = part[i];
                }
            }
            __syncthreads();
            if (tid < 128) {
                const float* bp = (const float*)(sm + R1) + tid * 4;
                float qv = __ldg(bf2 + a) + bp[0] + bp[1] + bp[2] + bp[3];
                out[(size_t)a * 65536 + (size_t)tile * 128 + tid] = qv;
            }
        }
    }
}

// ------------------------------------------------------------------ launcher
extern "C" void kernel_launch(void* const* d_in, const int* in_sizes, int n_in,
                              void* d_out, int out_size) {
    const float* obs = (const float*)d_in[0];
    const float* act = (const float*)d_in[1];
    const float* Wg  = (const float*)d_in[2];
    const float* bg  = (const float*)d_in[3];
    // d_in[4]=Wq, d_in[5]=Wk: dead (softmax over size-1 axis == 1)
    const float* Wv  = (const float*)d_in[6];
    const float* bv  = (const float*)d_in[7];
    const float* Wf1 = (const float*)d_in[8];
    const float* bf1 = (const float*)d_in[9];
    const float* Wf2 = (const float*)d_in[10];
    const float* bf2 = (const float*)d_in[11];
    float* out = (float*)d_out;

    cudaFuncSetAttribute(critic_main, cudaFuncAttributeMaxDynamicSharedMemorySize,
                         SMEM_TOTAL);
    prep_kernel<<<(NPREP + 255) / 256, 256>>>(Wg, Wv, Wf1);
    critic_main<<<512, 256, SMEM_TOTAL>>>(obs, act, bg, bv, bf1, Wf2, bf2, out);
}

// round 6
// speedup vs baseline: 1.0025x; 1.0025x over previous
#include <cuda_runtime.h>
#include <cuda_bf16.h>
#include <cstdint>
#include <cstddef>

// smem regions (bytes, base-relative)
#define R0 0u          // x tile [128][168] hi|lo (86016) / e tile [128][136] hi|lo (69632)
#define R1 86016u      // weight tile: wg 86016, others 69632 ; f2 buf
#define R2 155648u     // xi tile [128][136] hi|lo (69632)  (pass2 only)
#define SMEM_TOTAL 225280
#define ST_X 336       // x row stride bytes (168 bf16)
#define ST_E 272       // e/xi/weight row stride bytes (136 bf16)

// ---------------------------------------------------------------- helpers
__device__ __forceinline__ uint32_t smem_to_u32(const void* p) {
    uint32_t a;
    asm("{ .reg .u64 t; cvta.to.shared.u64 t, %1; cvt.u32.u64 %0, t; }"
        : "=r"(a) : "l"(p));
    return a;
}
__device__ __forceinline__ float lrelu(float x) { return x > 0.f ? x : 0.01f * x; }
__device__ __forceinline__ uint32_t pk(__nv_bfloat16 a, __nv_bfloat16 b) {
    __nv_bfloat162 t; t.x = a; t.y = b;
    return *reinterpret_cast<uint32_t*>(&t);
}
// split two floats into bf16 hi-pair and lo-pair
__device__ __forceinline__ void sp2(float a, float b, uint32_t& h, uint32_t& l) {
    __nv_bfloat16 h0 = __float2bfloat16(a), h1 = __float2bfloat16(b);
    __nv_bfloat16 l0 = __float2bfloat16(a - __bfloat162float(h0));
    __nv_bfloat16 l1 = __float2bfloat16(b - __bfloat162float(h1));
    h = pk(h0, h1); l = pk(l0, l1);
}
__device__ __forceinline__ void cpy(void* dst, const void* src, int nbytes, int tid) {
    uint4* d4 = (uint4*)dst;
    const uint4* s4 = (const uint4*)src;
    int n = nbytes >> 4;
    for (int i = tid; i < n; i += 256) d4[i] = s4[i];
}

#define LDSM4(r, a) \
    asm volatile("ldmatrix.sync.aligned.m8n8.x4.shared.b16 {%0,%1,%2,%3}, [%4];" \
        : "=r"((r)[0]), "=r"((r)[1]), "=r"((r)[2]), "=r"((r)[3]) : "r"(a))

#define MMA(c, av, b0, b1) \
    asm volatile("mma.sync.aligned.m16n8k16.row.col.f32.bf16.bf16.f32 " \
        "{%0,%1,%2,%3},{%4,%5,%6,%7},{%8,%9},{%0,%1,%2,%3};" \
        : "+f"((c)[0]), "+f"((c)[1]), "+f"((c)[2]), "+f"((c)[3]) \
        : "r"((av)[0]), "r"((av)[1]), "r"((av)[2]), "r"((av)[3]), "r"(b0), "r"(b1))

// ------------------------------------------------------------------- scratch
__device__ __align__(16) char g_wg[8 * 86016];       // [n=128][k=168 pad] hi|lo
__device__ __align__(16) char g_wv[69632];           // [128][136] hi|lo
__device__ __align__(16) char g_wf1[8 * 139264];     // per agent: part0 hi|lo, part1 hi|lo
__device__ __align__(16) char g_escr[285212672];     // 512 tiles x 8 agents x 69632

// --------------------------------------------------------------- prep kernel
#define NWG (8 * 160 * 128)
#define NWV (128 * 128)
#define NWF (8 * 256 * 128)
#define NPREP (NWG + NWV + NWF)

__global__ void prep_kernel(const float* __restrict__ Wg,
                            const float* __restrict__ Wv,
                            const float* __restrict__ Wf1) {
    int i = blockIdx.x * blockDim.x + threadIdx.x;
    if (i >= NPREP) return;
    float v; char* base; int losz, n, k, str;
    if (i < NWG) {
        int a = i / 20480, r = i - a * 20480;
        k = r >> 7; n = r & 127;                       // k 0..159
        v = Wg[(size_t)a * 20480 + (size_t)k * 128 + n];
        base = g_wg + (size_t)a * 86016; losz = 43008; str = ST_X;
    } else if (i < NWG + NWV) {
        int t = i - NWG;
        k = t >> 7; n = t & 127;
        v = Wv[(size_t)(n >> 5) * 4096 + (size_t)k * 32 + (n & 31)];
        base = g_wv; losz = 34816; str = ST_E;
    } else {
        int t = i - NWG - NWV;
        int a = t >> 15, r = t & 32767;
        int ii = r >> 7; n = r & 127;
        int part = ii >> 7; k = ii & 127;
        v = Wf1[(size_t)a * 32768 + (size_t)ii * 128 + n];
        base = g_wf1 + (size_t)a * 139264 + (size_t)part * 69632;
        losz = 34816; str = ST_E;
    }
    __nv_bfloat16 h = __float2bfloat16(v);
    __nv_bfloat16 l = __float2bfloat16(v - __bfloat162float(h));
    *(__nv_bfloat16*)(base + (size_t)n * str + k * 2) = h;
    *(__nv_bfloat16*)(base + losz + (size_t)n * str + k * 2) = l;
}

// --------------------------------------------------------- warp-tiled GEMM
// C[128,128] (+)= A[128,K] * B[128,K]^T with 2-way bf16 split (hh+hl+lh).
// 8 warps: wm=wid&1 (64-row half), wn=wid>>1 (32-col quarter).
__device__ __forceinline__ void gemm_run(uint32_t sb,
                                         uint32_t aHi, uint32_t aLo, int aStr,
                                         uint32_t bHi, uint32_t bLo, int bStr,
                                         int nks, float (&acc)[4][4][4], bool init,
                                         int wm, int wn, int lane) {
    if (init)
#pragma unroll
        for (int im = 0; im < 4; im++)
#pragma unroll
            for (int in = 0; in < 4; in++)
#pragma unroll
                for (int e = 0; e < 4; e++) acc[im][in][e] = 0.f;
    uint32_t aRow = (uint32_t)(wm * 64 + (lane & 15));
    uint32_t bRow = (uint32_t)(wn * 32 + (lane & 15));
    uint32_t colo = (uint32_t)((lane >> 4) * 16);
    for (int ks = 0; ks < nks; ks++) {
        uint32_t co = (uint32_t)ks * 32 + colo;
        uint32_t ah[4][4], al[4][4], bh[2][4], bl[2][4];
#pragma unroll
        for (int im = 0; im < 4; im++) {
            uint32_t r = (aRow + im * 16) * (uint32_t)aStr + co;
            LDSM4(ah[im], sb + aHi + r);
            LDSM4(al[im], sb + aLo + r);
        }
#pragma unroll
        for (int ip = 0; ip < 2; ip++) {
            uint32_t r = (bRow + ip * 16) * (uint32_t)bStr + co;
            LDSM4(bh[ip], sb + bHi + r);
            LDSM4(bl[ip], sb + bLo + r);
        }
#pragma unroll
        for (int im = 0; im < 4; im++)
#pragma unroll
            for (int in = 0; in < 4; in++) {
                uint32_t b0h = bh[in >> 1][in & 1], b1h = bh[in >> 1][(in & 1) + 2];
                uint32_t b0l = bl[in >> 1][in & 1], b1l = bl[in >> 1][(in & 1) + 2];
                MMA(acc[im][in], ah[im], b0h, b1h);
                MMA(acc[im][in], ah[im], b0l, b1l);
                MMA(acc[im][in], al[im], b0h, b1h);
            }
    }
}

// ----------------------------------------------------------------- main
__global__ __launch_bounds__(256, 1)
void critic_main(const float* __restrict__ obs, const float* __restrict__ act,
                 const float* __restrict__ bg, const float* __restrict__ bvv,
                 const float* __restrict__ bf1, const float* __restrict__ wf2,
                 const float* __restrict__ bf2, float* __restrict__ out) {
    extern __shared__ __align__(16) char sm[];
    uint32_t sb = smem_to_u32(sm);
    int tid = threadIdx.x;
    int lane = tid & 31, wid = tid >> 5;
    int wm = wid & 1, wn = wid >> 1;
    int g = lane >> 2, t4 = lane & 3;
    int tile = blockIdx.x;

    float acc[4][4][4];
    float S[4][4][4];

    // ============================ PASS 1 ============================
    for (int a = 0; a < 8; a++) {
        __syncthreads();
        // load x rows -> padded hi/lo smem tile
        {
            int row = tid >> 1, half = tid & 1;
            size_t rb = (size_t)a * 65536 + (size_t)tile * 128 + row;
            const float4* op = (const float4*)(obs + rb * 128) + half * 16;
            const float4* ap = (const float4*)(act + rb * 32) + half * 4;
            char* hb = sm + R0 + (size_t)row * ST_X;
            char* lb = hb + 43008;
#pragma unroll 4
            for (int i = 0; i < 16; i++) {
                float4 f = __ldg(op + i);
                int k = half * 64 + i * 4;
                uint32_t h0, l0, h1, l1;
                sp2(f.x, f.y, h0, l0); sp2(f.z, f.w, h1, l1);
                *(uint2*)(hb + k * 2) = make_uint2(h0, h1);
                *(uint2*)(lb + k * 2) = make_uint2(l0, l1);
            }
#pragma unroll
            for (int i = 0; i < 4; i++) {
                float4 f = __ldg(ap + i);
                int k = 128 + half * 16 + i * 4;
                uint32_t h0, l0, h1, l1;
                sp2(f.x, f.y, h0, l0); sp2(f.z, f.w, h1, l1);
                *(uint2*)(hb + k * 2) = make_uint2(h0, h1);
                *(uint2*)(lb + k * 2) = make_uint2(l0, l1);
            }
        }
        cpy(sm + R1, g_wg + (size_t)a * 86016, 86016, tid);
        __syncthreads();
        gemm_run(sb, R0, R0 + 43008, ST_X, R1, R1 + 43008, ST_X, 10, acc, true, wm, wn, lane);
        __syncthreads();
        // e = lrelu(acc + bg) -> hi/lo smem tile (overwrites x)
        {
            const float* bga = bg + a * 128;
#pragma unroll
            for (int im = 0; im < 4; im++)
#pragma unroll
                for (int in = 0; in < 4; in++) {
                    int c = wn * 32 + in * 8 + t4 * 2;
                    int r0 = wm * 64 + im * 16 + g;
                    float b0 = __ldg(bga + c), b1 = __ldg(bga + c + 1);
                    uint32_t h, l;
                    sp2(lrelu(acc[im][in][0] + b0), lrelu(acc[im][in][1] + b1), h, l);
                    *(uint32_t*)(sm + R0 + (size_t)r0 * ST_E + c * 2) = h;
                    *(uint32_t*)(sm + R0 + 34816 + (size_t)r0 * ST_E + c * 2) = l;
                    sp2(lrelu(acc[im][in][2] + b0), lrelu(acc[im][in][3] + b1), h, l);
                    *(uint32_t*)(sm + R0 + (size_t)(r0 + 8) * ST_E + c * 2) = h;
                    *(uint32_t*)(sm + R0 + 34816 + (size_t)(r0 + 8) * ST_E + c * 2) = l;
                }
        }
        __syncthreads();
        cpy(g_escr + ((size_t)tile * 8 + a) * 69632, sm + R0, 69632, tid);
        cpy(sm + R1, g_wv, 69632, tid);
        __syncthreads();
        gemm_run(sb, R0, R0 + 34816, ST_E, R1, R1 + 34816, ST_E, 8, acc, true, wm, wn, lane);
        // S += lrelu(v + bv)
#pragma unroll
        for (int im = 0; im < 4; im++)
#pragma unroll
            for (int in = 0; in < 4; in++) {
                int c = wn * 32 + in * 8 + t4 * 2;
                float b0 = __ldg(bvv + c), b1 = __ldg(bvv + c + 1);
                float v0 = lrelu(acc[im][in][0] + b0), v1 = lrelu(acc[im][in][1] + b1);
                float v2 = lrelu(acc[im][in][2] + b0), v3 = lrelu(acc[im][in][3] + b1);
                if (a == 0) {
                    S[im][in][0] = v0; S[im][in][1] = v1;
                    S[im][in][2] = v2; S[im][in][3] = v3;
                } else {
                    S[im][in][0] += v0; S[im][in][1] += v1;
                    S[im][in][2] += v2; S[im][in][3] += v3;
                }
            }
    }

    // ============================ PASS 2 ============================
    for (int a = 0; a < 8; a++) {
        __syncthreads();
        cpy(sm + R0, g_escr + ((size_t)tile * 8 + a) * 69632, 69632, tid);
        cpy(sm + R1, g_wv, 69632, tid);
        __syncthreads();
        gemm_run(sb, R0, R0 + 34816, ST_E, R1, R1 + 34816, ST_E, 8, acc, true, wm, wn, lane);
        // xi = S - lrelu(v+bv) -> R2 hi/lo
#pragma unroll
        for (int im = 0; im < 4; im++)
#pragma unroll
            for (int in = 0; in < 4; in++) {
                int c = wn * 32 + in * 8 + t4 * 2;
                int r0 = wm * 64 + im * 16 + g;
                float b0 = __ldg(bvv + c), b1 = __ldg(bvv + c + 1);
                float x0 = S[im][in][0] - lrelu(acc[im][in][0] + b0);
                float x1 = S[im][in][1] - lrelu(acc[im][in][1] + b1);
                float x2 = S[im][in][2] - lrelu(acc[im][in][2] + b0);
                float x3 = S[im][in][3] - lrelu(acc[im][in][3] + b1);
                uint32_t h, l;
                sp2(x0, x1, h, l);
                *(uint32_t*)(sm + R2 + (size_t)r0 * ST_E + c * 2) = h;
                *(uint32_t*)(sm + R2 + 34816 + (size_t)r0 * ST_E + c * 2) = l;
                sp2(x2, x3, h, l);
                *(uint32_t*)(sm + R2 + (size_t)(r0 + 8) * ST_E + c * 2) = h;
                *(uint32_t*)(sm + R2 + 34816 + (size_t)(r0 + 8) * ST_E + c * 2) = l;
            }
        __syncthreads();
        cpy(sm + R1, g_wf1 + (size_t)a * 139264, 69632, tid);   // Wf1 part0 (xi)
        __syncthreads();
        gemm_run(sb, R2, R2 + 34816, ST_E, R1, R1 + 34816, ST_E, 8, acc, true, wm, wn, lane);
        __syncthreads();
        cpy(sm + R1, g_wf1 + (size_t)a * 139264 + 69632, 69632, tid);  // part1 (e)
        __syncthreads();
        gemm_run(sb, R0, R0 + 34816, ST_E, R1, R1 + 34816, ST_E, 8, acc, false, wm, wn, lane);
        __syncthreads();
        // f2: per-row dot( lrelu(h1+bf1), wf2 )
        {
            float part[8];
#pragma unroll
            for (int i = 0; i < 8; i++) part[i] = 0.f;
            const float* b1a = bf1 + a * 128;
            const float* w2a = wf2 + a * 128;
#pragma unroll
            for (int im = 0; im < 4; im++)
#pragma unroll
                for (int in = 0; in < 4; in++) {
                    int c = wn * 32 + in * 8 + t4 * 2;
                    float b0 = __ldg(b1a + c), b1 = __ldg(b1a + c + 1);
                    float w0 = __ldg(w2a + c), w1 = __ldg(w2a + c + 1);
                    part[im * 2 + 0] += lrelu(acc[im][in][0] + b0) * w0
                                      + lrelu(acc[im][in][1] + b1) * w1;
                    part[im * 2 + 1] += lrelu(acc[im][in][2] + b0) * w0
                                      + lrelu(acc[im][in][3] + b1) * w1;
                }
#pragma unroll
            for (int i = 0; i < 8; i++) {
                part[i] += __shfl_xor_sync(0xffffffffu, part[i], 1);
                part[i] += __shfl_xor_sync(0xffffffffu, part[i], 2);
            }
            if (t4 == 0) {
#pragma unroll
                for (int i = 0; i < 8; i++) {
                    int row = wm * 64 + (i >> 1) * 16 + g + (i & 1) * 8;
                    ((float*)(sm + R1))[row * 4 + wn] = part[i];
                }
            }
            __syncthreads();
            if (tid < 128) {
                const float* bp = (const float*)(sm + R1) + tid * 4;
                float qv = __ldg(bf2 + a) + bp[0] + bp[1] + bp[2] + bp[3];
                out[(size_t)a * 65536 + (size_t)tile * 128 + tid] = qv;
            }
        }
    }
}

// ------------------------------------------------------------------ launcher
extern "C" void kernel_launch(void* const* d_in, const int* in_sizes, int n_in,
                              void* d_out, int out_size) {
    const float* obs = (const float*)d_in[0];
    const float* act = (const float*)d_in[1];
    const float* Wg  = (const float*)d_in[2];
    const float* bg  = (const float*)d_in[3];
    // d_in[4]=Wq, d_in[5]=Wk: dead (softmax over size-1 axis == 1)
    const float* Wv  = (const float*)d_in[6];
    const float* bv  = (const float*)d_in[7];
    const float* Wf1 = (const float*)d_in[8];
    const float* bf1 = (const float*)d_in[9];
    const float* Wf2 = (const float*)d_in[10];
    const float* bf2 = (const float*)d_in[11];
    float* out = (float*)d_out;

    cudaFuncSetAttribute(critic_main, cudaFuncAttributeMaxDynamicSharedMemorySize,
                         SMEM_TOTAL);
    prep_kernel<<<(NPREP + 255) / 256, 256>>>(Wg, Wv, Wf1);
    critic_main<<<512, 256, SMEM_TOTAL>>>(obs, act, bg, bv, bf1, Wf2, bf2, out);
}

// round 7
// speedup vs baseline: 1.2275x; 1.2244x over previous
#include <cuda_runtime.h>
#include <cuda_bf16.h>
#include <cstdint>
#include <cstddef>

// smem layout (bytes, base-relative)
//  A  region:      0 .. 86016   x tile (ST_X, hi|lo at +43008) / e tile (ST_E, hi|lo at +34816)
//  CB0 chunk buf:  86016 .. 122880   (36864: hi 18432 | lo 18432)
//  CB1 chunk buf:  122880 .. 159744
//  XI region:      159744 .. 229376  xi tile (ST_E, hi|lo at +34816); also f2 buffer
#define CB0_OFF 86016u
#define CB1_OFF 122880u
#define XI_OFF  159744u
#define SMEM_TOTAL 229376
#define ST_X 336      // x row stride bytes (168 bf16)
#define ST_E 272      // e/xi row stride bytes (136 bf16)
#define ST_W 144      // weight chunk row stride bytes (72 bf16)
#define CHUNK_B 36864
#define NCHUNKS 72    // 8 agents * (3 wg + 2 wv) + 8 agents * (2 f1a + 2 f1b)

// ---------------------------------------------------------------- helpers
__device__ __forceinline__ uint32_t smem_to_u32(const void* p) {
    uint32_t a;
    asm("{ .reg .u64 t; cvta.to.shared.u64 t, %1; cvt.u32.u64 %0, t; }"
        : "=r"(a) : "l"(p));
    return a;
}
__device__ __forceinline__ float lrelu(float x) { return x > 0.f ? x : 0.01f * x; }
__device__ __forceinline__ uint32_t pk(__nv_bfloat16 a, __nv_bfloat16 b) {
    __nv_bfloat162 t; t.x = a; t.y = b;
    return *reinterpret_cast<uint32_t*>(&t);
}
__device__ __forceinline__ void sp2(float a, float b, uint32_t& h, uint32_t& l) {
    __nv_bfloat16 h0 = __float2bfloat16(a), h1 = __float2bfloat16(b);
    __nv_bfloat16 l0 = __float2bfloat16(a - __bfloat162float(h0));
    __nv_bfloat16 l1 = __float2bfloat16(b - __bfloat162float(h1));
    h = pk(h0, h1); l = pk(l0, l1);
}
__device__ __forceinline__ void cpy(void* dst, const void* src, int nbytes, int tid) {
    uint4* d4 = (uint4*)dst;
    const uint4* s4 = (const uint4*)src;
    int n = nbytes >> 4;
    for (int i = tid; i < n; i += 256) d4[i] = s4[i];
}

#define LDSM4(r, a) \
    asm volatile("ldmatrix.sync.aligned.m8n8.x4.shared.b16 {%0,%1,%2,%3}, [%4];" \
        : "=r"((r)[0]), "=r"((r)[1]), "=r"((r)[2]), "=r"((r)[3]) : "r"(a))

#define MMA(c, av, b0, b1) \
    asm volatile("mma.sync.aligned.m16n8k16.row.col.f32.bf16.bf16.f32 " \
        "{%0,%1,%2,%3},{%4,%5,%6,%7},{%8,%9},{%0,%1,%2,%3};" \
        : "+f"((c)[0]), "+f"((c)[1]), "+f"((c)[2]), "+f"((c)[3]) \
        : "r"((av)[0]), "r"((av)[1]), "r"((av)[2]), "r"((av)[3]), "r"(b0), "r"(b1))

#define CPWAIT1() asm volatile("cp.async.wait_group 1;" ::: "memory")
#define CPWAIT0() asm volatile("cp.async.wait_group 0;" ::: "memory")
#define CPCOMMIT() asm volatile("cp.async.commit_group;" ::: "memory")

// ------------------------------------------------------------------- scratch
__device__ __align__(16) char g_wg[8 * 110592];     // per agent: 3 chunks (hi|lo 18432 each)
__device__ __align__(16) char g_wv[73728];          // 2 chunks
__device__ __align__(16) char g_wf1[8 * 147456];    // per agent: f1a c0,c1, f1b c0,c1
__device__ __align__(16) char g_escr[285212672];    // 512 tiles x 8 agents x 69632 (e hi|lo image)
__device__ __align__(16) char g_vscr[268435456];    // 512 tiles x 8 agents x 65536 (v fp32 [row][col])

// --------------------------------------------------------------- prep kernel
#define NWG (8 * 160 * 128)
#define NWV (128 * 128)
#define NWF (8 * 256 * 128)
#define NPREP (NWG + NWV + NWF)

__global__ void prep_kernel(const float* __restrict__ Wg,
                            const float* __restrict__ Wv,
                            const float* __restrict__ Wf1) {
    int i = blockIdx.x * blockDim.x + threadIdx.x;
    if (i >= NPREP) return;
    float v; char* base; int n, k;
    if (i < NWG) {
        int a = i / 20480, r = i - a * 20480;
        k = r >> 7; n = r & 127;
        v = Wg[(size_t)a * 20480 + (size_t)k * 128 + n];
        base = g_wg + (size_t)a * 110592 + (size_t)(k >> 6) * CHUNK_B;
    } else if (i < NWG + NWV) {
        int t = i - NWG;
        k = t >> 7; n = t & 127;
        v = Wv[(size_t)(n >> 5) * 4096 + (size_t)k * 32 + (n & 31)];
        base = g_wv + (size_t)(k >> 6) * CHUNK_B;
    } else {
        int t = i - NWG - NWV;
        int a = t >> 15, r = t & 32767;
        int ii = r >> 7; n = r & 127;
        int p = ii >> 7; k = ii & 127;
        v = Wf1[(size_t)a * 32768 + (size_t)ii * 128 + n];
        base = g_wf1 + (size_t)a * 147456 + (size_t)(p * 2 + (k >> 6)) * CHUNK_B;
    }
    int kk = k & 63;
    __nv_bfloat16 h = __float2bfloat16(v);
    __nv_bfloat16 l = __float2bfloat16(v - __bfloat162float(h));
    *(__nv_bfloat16*)(base + (size_t)n * ST_W + kk * 2) = h;
    *(__nv_bfloat16*)(base + 18432 + (size_t)n * ST_W + kk * 2) = l;
}

// ---------------------------------------------------------- chunk pipeline
__device__ __forceinline__ const char* chunk_src(int i) {
    if (i < 40) {
        int a = i / 5, c = i - a * 5;
        return (c < 3) ? g_wg + (size_t)a * 110592 + (size_t)c * CHUNK_B
                       : g_wv + (size_t)(c - 3) * CHUNK_B;
    }
    int j = i - 40;
    int a = j >> 2, c = j & 3;
    return g_wf1 + (size_t)a * 147456 + (size_t)c * CHUNK_B;
}

__device__ __forceinline__ void prefetch_chunk(uint32_t sb, int idx, int tid) {
    const char* s = chunk_src(idx) + (size_t)tid * 16;
    uint32_t d = sb + ((idx & 1) ? CB1_OFF : CB0_OFF) + (uint32_t)tid * 16u;
#pragma unroll
    for (int i = 0; i < 9; i++) {
        asm volatile("cp.async.cg.shared.global [%0], [%1], 16;"
                     :: "r"(d + (uint32_t)i * 4096u), "l"(s + (size_t)i * 4096)
                     : "memory");
    }
    CPCOMMIT();
}

// one weight chunk's worth of GEMM: C += A[:, kbase*16 ...] * Bchunk^T
__device__ __forceinline__ void gemm_chunk(uint32_t sb, uint32_t aHi, uint32_t aLo,
                                           int aStr, uint32_t bOff, int nks, int kbase,
                                           float (&acc)[4][4][4], bool init,
                                           int wm, int wn, int lane) {
    if (init)
#pragma unroll
        for (int im = 0; im < 4; im++)
#pragma unroll
            for (int in = 0; in < 4; in++)
#pragma unroll
                for (int e = 0; e < 4; e++) acc[im][in][e] = 0.f;
    uint32_t aRow = (uint32_t)(wm * 64 + (lane & 15));
    uint32_t bRow = (uint32_t)(wn * 32 + (lane & 15));
    uint32_t colo = (uint32_t)((lane >> 4) * 16);
    for (int ksl = 0; ksl < nks; ksl++) {
        uint32_t coA = (uint32_t)(kbase + ksl) * 32 + colo;
        uint32_t coB = (uint32_t)ksl * 32 + colo;
        uint32_t ah[4][4], al[4][4], bh[2][4], bl[2][4];
#pragma unroll
        for (int im = 0; im < 4; im++) {
            uint32_t r = (aRow + im * 16) * (uint32_t)aStr + coA;
            LDSM4(ah[im], sb + aHi + r);
            LDSM4(al[im], sb + aLo + r);
        }
#pragma unroll
        for (int ip = 0; ip < 2; ip++) {
            uint32_t r = (bRow + ip * 16) * (uint32_t)ST_W + coB;
            LDSM4(bh[ip], sb + bOff + r);
            LDSM4(bl[ip], sb + bOff + 18432u + r);
        }
#pragma unroll
        for (int im = 0; im < 4; im++)
#pragma unroll
            for (int in = 0; in < 4; in++) {
                uint32_t b0h = bh[in >> 1][in & 1], b1h = bh[in >> 1][(in & 1) + 2];
                uint32_t b0l = bl[in >> 1][in & 1], b1l = bl[in >> 1][(in & 1) + 2];
                MMA(acc[im][in], ah[im], b0h, b1h);
                MMA(acc[im][in], ah[im], b0l, b1l);
                MMA(acc[im][in], al[im], b0h, b1h);
            }
    }
}

__device__ __forceinline__ void consume_chunk(uint32_t sb, int& cc, int& pc,
                                              uint32_t aHi, uint32_t aLo, int aStr,
                                              int nks, int kbase,
                                              float (&acc)[4][4][4], bool init,
                                              int wm, int wn, int lane, int tid) {
    if (pc - cc >= 2) CPWAIT1(); else CPWAIT0();
    __syncthreads();
    uint32_t bOff = (cc & 1) ? CB1_OFF : CB0_OFF;
    gemm_chunk(sb, aHi, aLo, aStr, bOff, nks, kbase, acc, init, wm, wn, lane);
    __syncthreads();
    if (pc < NCHUNKS) { prefetch_chunk(sb, pc, tid); pc++; }
    cc++;
}

// ----------------------------------------------------------------- main
__global__ __launch_bounds__(256, 1)
void critic_main(const float* __restrict__ obs, const float* __restrict__ act,
                 const float* __restrict__ bg, const float* __restrict__ bvv,
                 const float* __restrict__ bf1, const float* __restrict__ wf2,
                 const float* __restrict__ bf2, float* __restrict__ out) {
    extern __shared__ __align__(16) char sm[];
    uint32_t sb = smem_to_u32(sm);
    int tid = threadIdx.x;
    int lane = tid & 31, wid = tid >> 5;
    int wm = wid & 1, wn = wid >> 1;
    int g = lane >> 2, t4 = lane & 3;
    int tile = blockIdx.x;

    float acc[4][4][4];
    float S[4][4][4];

    int cc = 0, pc = 0;
    prefetch_chunk(sb, pc, tid); pc++;
    prefetch_chunk(sb, pc, tid); pc++;

    // ============================ PASS 1 ============================
    for (int a = 0; a < 8; a++) {
        // x rows -> A region (split hi/lo). 2 threads per row.
        {
            int row = tid >> 1, half = tid & 1;
            size_t rb = (size_t)a * 65536 + (size_t)tile * 128 + row;
            const float4* op = (const float4*)(obs + rb * 128) + half * 16;
            const float4* ap = (const float4*)(act + rb * 32) + half * 4;
            char* hb = sm + (size_t)row * ST_X;
            char* lb = hb + 43008;
#pragma unroll 4
            for (int i = 0; i < 16; i++) {
                float4 f = __ldg(op + i);
                int k = half * 64 + i * 4;
                uint32_t h0, l0, h1, l1;
                sp2(f.x, f.y, h0, l0); sp2(f.z, f.w, h1, l1);
                *(uint2*)(hb + k * 2) = make_uint2(h0, h1);
                *(uint2*)(lb + k * 2) = make_uint2(l0, l1);
            }
#pragma unroll
            for (int i = 0; i < 4; i++) {
                float4 f = __ldg(ap + i);
                int k = 128 + half * 16 + i * 4;
                uint32_t h0, l0, h1, l1;
                sp2(f.x, f.y, h0, l0); sp2(f.z, f.w, h1, l1);
                *(uint2*)(hb + k * 2) = make_uint2(h0, h1);
                *(uint2*)(lb + k * 2) = make_uint2(l0, l1);
            }
        }
        // g GEMM: K=160 = chunks of 4,4,2 k-steps
        consume_chunk(sb, cc, pc, 0u, 43008u, ST_X, 4, 0, acc, true,  wm, wn, lane, tid);
        consume_chunk(sb, cc, pc, 0u, 43008u, ST_X, 4, 4, acc, false, wm, wn, lane, tid);
        consume_chunk(sb, cc, pc, 0u, 43008u, ST_X, 2, 8, acc, false, wm, wn, lane, tid);

        // e = lrelu(acc + bg) -> A region (ST_E image)
        {
            const float* bga = bg + a * 128;
#pragma unroll
            for (int im = 0; im < 4; im++)
#pragma unroll
                for (int in = 0; in < 4; in++) {
                    int c = wn * 32 + in * 8 + t4 * 2;
                    int r0 = wm * 64 + im * 16 + g;
                    float b0 = __ldg(bga + c), b1 = __ldg(bga + c + 1);
                    uint32_t h, l;
                    sp2(lrelu(acc[im][in][0] + b0), lrelu(acc[im][in][1] + b1), h, l);
                    *(uint32_t*)(sm + (size_t)r0 * ST_E + c * 2) = h;
                    *(uint32_t*)(sm + 34816 + (size_t)r0 * ST_E + c * 2) = l;
                    sp2(lrelu(acc[im][in][2] + b0), lrelu(acc[im][in][3] + b1), h, l);
                    *(uint32_t*)(sm + (size_t)(r0 + 8) * ST_E + c * 2) = h;
                    *(uint32_t*)(sm + 34816 + (size_t)(r0 + 8) * ST_E + c * 2) = l;
                }
        }
        __syncthreads();
        cpy(g_escr + ((size_t)tile * 8 + a) * 69632, sm, 69632, tid);

        // v GEMM: K=128 = 2 chunks of 4
        consume_chunk(sb, cc, pc, 0u, 34816u, ST_E, 4, 0, acc, true,  wm, wn, lane, tid);
        consume_chunk(sb, cc, pc, 0u, 34816u, ST_E, 4, 4, acc, false, wm, wn, lane, tid);

        // S += lrelu(v + bv); store v fp32 to scratch
        {
            float* vdst = (float*)(g_vscr + ((size_t)tile * 8 + a) * 65536);
#pragma unroll
            for (int im = 0; im < 4; im++)
#pragma unroll
                for (int in = 0; in < 4; in++) {
                    int c = wn * 32 + in * 8 + t4 * 2;
                    int r0 = wm * 64 + im * 16 + g;
                    float b0 = __ldg(bvv + c), b1 = __ldg(bvv + c + 1);
                    float v0 = lrelu(acc[im][in][0] + b0), v1 = lrelu(acc[im][in][1] + b1);
                    float v2 = lrelu(acc[im][in][2] + b0), v3 = lrelu(acc[im][in][3] + b1);
                    if (a == 0) {
                        S[im][in][0] = v0; S[im][in][1] = v1;
                        S[im][in][2] = v2; S[im][in][3] = v3;
                    } else {
                        S[im][in][0] += v0; S[im][in][1] += v1;
                        S[im][in][2] += v2; S[im][in][3] += v3;
                    }
                    *(float2*)(vdst + (size_t)r0 * 128 + c) = make_float2(v0, v1);
                    *(float2*)(vdst + (size_t)(r0 + 8) * 128 + c) = make_float2(v2, v3);
                }
        }
    }

    // ============================ PASS 2 ============================
    for (int a = 0; a < 8; a++) {
        __syncthreads();
        cpy(sm, g_escr + ((size_t)tile * 8 + a) * 69632, 69632, tid);
        __syncthreads();
        // xi = S - v (v from scratch), split -> XI region
        {
            const float* vsrc = (const float*)(g_vscr + ((size_t)tile * 8 + a) * 65536);
#pragma unroll
            for (int im = 0; im < 4; im++)
#pragma unroll
                for (int in = 0; in < 4; in++) {
                    int c = wn * 32 + in * 8 + t4 * 2;
                    int r0 = wm * 64 + im * 16 + g;
                    float2 va = __ldg((const float2*)(vsrc + (size_t)r0 * 128 + c));
                    float2 vb = __ldg((const float2*)(vsrc + (size_t)(r0 + 8) * 128 + c));
                    uint32_t h, l;
                    sp2(S[im][in][0] - va.x, S[im][in][1] - va.y, h, l);
                    *(uint32_t*)(sm + XI_OFF + (size_t)r0 * ST_E + c * 2) = h;
                    *(uint32_t*)(sm + XI_OFF + 34816 + (size_t)r0 * ST_E + c * 2) = l;
                    sp2(S[im][in][2] - vb.x, S[im][in][3] - vb.y, h, l);
                    *(uint32_t*)(sm + XI_OFF + (size_t)(r0 + 8) * ST_E + c * 2) = h;
                    *(uint32_t*)(sm + XI_OFF + 34816 + (size_t)(r0 + 8) * ST_E + c * 2) = l;
                }
        }
        // f1 = Wf1a * xi + Wf1b * e  (accumulate across the two GEMMs)
        consume_chunk(sb, cc, pc, XI_OFF, XI_OFF + 34816u, ST_E, 4, 0, acc, true,  wm, wn, lane, tid);
        consume_chunk(sb, cc, pc, XI_OFF, XI_OFF + 34816u, ST_E, 4, 4, acc, false, wm, wn, lane, tid);
        consume_chunk(sb, cc, pc, 0u, 34816u, ST_E, 4, 0, acc, false, wm, wn, lane, tid);
        consume_chunk(sb, cc, pc, 0u, 34816u, ST_E, 4, 4, acc, false, wm, wn, lane, tid);

        // f2: qv = bf2 + sum_c lrelu(h1 + bf1) * wf2
        {
            float part[8];
#pragma unroll
            for (int i = 0; i < 8; i++) part[i] = 0.f;
            const float* b1a = bf1 + a * 128;
            const float* w2a = wf2 + a * 128;
#pragma unroll
            for (int im = 0; im < 4; im++)
#pragma unroll
                for (int in = 0; in < 4; in++) {
                    int c = wn * 32 + in * 8 + t4 * 2;
                    float b0 = __ldg(b1a + c), b1 = __ldg(b1a + c + 1);
                    float w0 = __ldg(w2a + c), w1 = __ldg(w2a + c + 1);
                    part[im * 2 + 0] += lrelu(acc[im][in][0] + b0) * w0
                                      + lrelu(acc[im][in][1] + b1) * w1;
                    part[im * 2 + 1] += lrelu(acc[im][in][2] + b0) * w0
                                      + lrelu(acc[im][in][3] + b1) * w1;
                }
#pragma unroll
            for (int i = 0; i < 8; i++) {
                part[i] += __shfl_xor_sync(0xffffffffu, part[i], 1);
                part[i] += __shfl_xor_sync(0xffffffffu, part[i], 2);
            }
            if (t4 == 0) {
#pragma unroll
                for (int i = 0; i < 8; i++) {
                    int row = wm * 64 + (i >> 1) * 16 + g + (i & 1) * 8;
                    ((float*)(sm + XI_OFF))[row * 4 + wn] = part[i];
                }
            }
            __syncthreads();
            if (tid < 128) {
                const float* bp = (const float*)(sm + XI_OFF) + tid * 4;
                float qv = __ldg(bf2 + a) + bp[0] + bp[1] + bp[2] + bp[3];
                out[(size_t)a * 65536 + (size_t)tile * 128 + tid] = qv;
            }
        }
    }
}

// ------------------------------------------------------------------ launcher
extern "C" void kernel_launch(void* const* d_in, const int* in_sizes, int n_in,
                              void* d_out, int out_size) {
    const float* obs = (const float*)d_in[0];
    const float* act = (const float*)d_in[1];
    const float* Wg  = (const float*)d_in[2];
    // d_in[4]=Wq, d_in[5]=Wk: dead (softmax over size-1 axis == 1)
    const float* bg  = (const float*)d_in[3];
    const float* Wv  = (const float*)d_in[6];
    const float* bv  = (const float*)d_in[7];
    const float* Wf1 = (const float*)d_in[8];
    const float* bf1 = (const float*)d_in[9];
    const float* Wf2 = (const float*)d_in[10];
    const float* bf2 = (const float*)d_in[11];
    float* out = (float*)d_out;

    cudaFuncSetAttribute(critic_main, cudaFuncAttributeMaxDynamicSharedMemorySize,
                         SMEM_TOTAL);
    prep_kernel<<<(NPREP + 255) / 256, 256>>>(Wg, Wv, Wf1);
    critic_main<<<512, 256, SMEM_TOTAL>>>(obs, act, bg, bv, bf1, Wf2, bf2, out);
}